// round 16
// baseline (speedup 1.0000x reference)
#include <cuda_runtime.h>
#include <cuda_fp16.h>
#include <stdint.h>
#include <math.h>

#define N_TOK 8192
#define D_IN  512
#define HID   256
#define C_OUT 256
#define NCHUNK 128           // one stats chunk per 64-row warp block
#define NH (N_TOK * HID)
#define NSPLIT 4             // PV split-K slices

// ---- scratch (static __device__, allocation-free) ----
__device__ __half g_h  [NH];
__device__ __half g_qkv[N_TOK * 3 * HID];          // [8192][768] q|k|v
__device__ __half g_hs [NSPLIT * NH];              // PV slice partials (fp16)
__device__ __half g_S  [(size_t)N_TOK * N_TOK];    // Etilde = exp(S*scale - m_chunk)
__device__ float  g_pm [NCHUNK * N_TOK];
__device__ float  g_pZ [NCHUNK * N_TOK];
__device__ __half g_c  [NCHUNK * N_TOK];           // exp(pm - LZ)
__device__ __half g_W1t[HID * D_IN];
__device__ __half g_Wqkvt[3 * HID * HID];
__device__ float  g_bqkv[3 * HID];
__device__ __half g_W2t[C_OUT * HID];
__device__ __half g_vT [HID * N_TOK];              // (v*(1-a))^T : [256][8192]

__device__ __forceinline__ uint32_t smem_u32(const void* p) {
    uint32_t a;
    asm("{ .reg .u64 t; cvta.to.shared.u64 t, %1; cvt.u32.u64 %0, t; }"
        : "=r"(a) : "l"(p));
    return a;
}

__device__ __forceinline__ uint2 pack_f4(float4 v) {
    __half2 h0 = __floats2half2_rn(v.x, v.y);
    __half2 h1 = __floats2half2_rn(v.z, v.w);
    uint2 u;
    u.x = *reinterpret_cast<uint32_t*>(&h0);
    u.y = *reinterpret_cast<uint32_t*>(&h1);
    return u;
}

#define LDSM_X4(r0, r1, r2, r3, addr) \
    asm volatile("ldmatrix.sync.aligned.m8n8.x4.shared.b16 {%0,%1,%2,%3}, [%4];" \
        : "=r"(r0), "=r"(r1), "=r"(r2), "=r"(r3) : "r"(addr))

#define MMA_16816(c, a, b) \
    asm volatile("mma.sync.aligned.m16n8k16.row.col.f32.f16.f16.f32 " \
        "{%0,%1,%2,%3}, {%4,%5,%6,%7}, {%8,%9}, {%0,%1,%2,%3};" \
        : "+f"((c)[0]), "+f"((c)[1]), "+f"((c)[2]), "+f"((c)[3]) \
        : "r"((a)[0]), "r"((a)[1]), "r"((a)[2]), "r"((a)[3]), \
          "r"((b)[0]), "r"((b)[1]))

#define CP_ASYNC16(dst, src) \
    asm volatile("cp.async.cg.shared.global [%0], [%1], 16;" \
        :: "r"(dst), "l"(src) : "memory")
#define CP_COMMIT() asm volatile("cp.async.commit_group;" ::: "memory")
#define CP_WAIT1()  asm volatile("cp.async.wait_group 1;" ::: "memory")

#define SSTR 40    // smem row stride in halves; conflict-free LDSM phases
#define NSTG 3     // pipeline stages
#define TILE_H (128 * SSTR)                 // halves per tile buffer
#define SMEM3 (NSTG * 2 * TILE_H * 2)       // bytes of dynamic smem (61440)

// ---------------------------------------------------------------------------
// fp16 NT GEMM: C[M,N] = A[M,K'] @ Bt[N,K']^T, K' slice per grid.z.
// MODE 0: C = acc + bias[col]
// MODE 1 + STATS: per-warp(64-row) column softmax store + chunk stats pm/pZ.
// MODE 3: plain fp16 store of acc to slice buffer Ch + z*NH (split-K partial)
// AH/BH: A/B gmem fp16 (else f32). CH: C stored fp16.
// MUL_A: A (fp16) multiplied by ctab[rowchunk][kcol] during staging.
// SUMS:  A = (*aptr)*Ah + sum of NSPLIT fp16 slice buffers (gated residual).
// fp16 A/B without MUL/SUMS stage via cp.async (3-stage ring); others via
// register prefetch one iter ahead.
// CTA 128x128, BK=32, 128 threads (4 warps 2x2), warp tile 64x64.
// ---------------------------------------------------------------------------
template <int MODE, bool MUL_A, bool STATS, bool AH, bool BH, bool CH, bool SUMS>
__global__ __launch_bounds__(128, 2) void hmma_gemm(
    const void* __restrict__ Av, const void* __restrict__ Bv,
    void* __restrict__ Cv, int N, int K, int lda, int ldb,
    const float* __restrict__ bias, float scale,
    const __half* __restrict__ ctab,
    float* __restrict__ pm, float* __restrict__ pZ,
    const void* __restrict__ slices, const float* __restrict__ aptr)
{
    constexpr bool A_CP = (AH && !MUL_A && !SUMS);  // A staged via cp.async
    constexpr bool B_CP = BH;                       // B staged via cp.async

    const float*  Af = (const float*)Av;
    const __half* Ah = (const __half*)Av;
    const float*  Bf = (const float*)Bv;
    const __half* Bh = (const __half*)Bv;
    const __half* Sl = (const __half*)slices;
    float*  Cf = (float*)Cv;
    __half* Ch = (__half*)Cv;

    extern __shared__ __half dynsm[];
    __half* const Abuf = dynsm;                    // [NSTG][TILE_H]
    __half* const Bbuf = dynsm + NSTG * TILE_H;    // [NSTG][TILE_H]

    const int tid  = threadIdx.x;
    const int lane = tid & 31;
    const int wid  = tid >> 5;          // 0..3
    const int wm   = wid >> 1;          // 0..1
    const int wn   = wid & 1;           // 0..1
    const int row0 = blockIdx.y * 128;
    const int col0 = blockIdx.x * 128;
    const int koff = blockIdx.z * K;

    const int h_r = tid >> 2;           // 0..31 (f16 staging, 4 passes)
    const int h_c = (tid & 3) * 8;
    const int a_r = tid >> 3;           // 0..15 (f32 staging, 8 passes)
    const int a_c = (tid & 7) * 4;

    __half2 av2 = __float2half2_rn(0.f);
    if (SUMS) av2 = __float2half2_rn(*aptr);

    float acc[4][8][4];
#pragma unroll
    for (int i = 0; i < 4; i++)
#pragma unroll
        for (int j = 0; j < 8; j++)
#pragma unroll
            for (int r = 0; r < 4; r++) acc[i][j][r] = 0.0f;

    uint2 aF[8], bF[8];
    uint4 aH[4];

    // reg-path LDG (issued early; consumed by stsR)
    auto ldgR = [&](int k0) {
        if (SUMS) {
#pragma unroll
            for (int l = 0; l < 4; l++) {
                int r = h_r + 32 * l;
                size_t base = (size_t)(row0 + r) * lda + koff + k0 + h_c;
                uint4 vh = *reinterpret_cast<const uint4*>(&Ah[base]);
                uint4 s0 = *reinterpret_cast<const uint4*>(&Sl[base]);
                uint4 s1 = *reinterpret_cast<const uint4*>(&Sl[(size_t)NH + base]);
                uint4 s2 = *reinterpret_cast<const uint4*>(&Sl[2 * (size_t)NH + base]);
                uint4 s3 = *reinterpret_cast<const uint4*>(&Sl[3 * (size_t)NH + base]);
                __half2* pv = reinterpret_cast<__half2*>(&vh);
                const __half2* p0 = reinterpret_cast<const __half2*>(&s0);
                const __half2* p1 = reinterpret_cast<const __half2*>(&s1);
                const __half2* p2 = reinterpret_cast<const __half2*>(&s2);
                const __half2* p3 = reinterpret_cast<const __half2*>(&s3);
#pragma unroll
                for (int t = 0; t < 4; t++) {
                    __half2 s = __hadd2(__hadd2(p0[t], p1[t]),
                                        __hadd2(p2[t], p3[t]));
                    pv[t] = __hfma2(pv[t], av2, s);
                }
                aH[l] = vh;
            }
        } else if (!AH) {
#pragma unroll
            for (int l = 0; l < 8; l++) {
                int r = a_r + 16 * l;
                aF[l] = pack_f4(*reinterpret_cast<const float4*>(
                    &Af[(size_t)(row0 + r) * lda + koff + k0 + a_c]));
            }
        } else if (MUL_A) {
#pragma unroll
            for (int l = 0; l < 4; l++) {
                int r = h_r + 32 * l;
                uint4 v = *reinterpret_cast<const uint4*>(
                    &Ah[(size_t)(row0 + r) * lda + koff + k0 + h_c]);
                int chunk = (row0 + r) >> 6;
                uint4 cu = *reinterpret_cast<const uint4*>(
                    &ctab[(size_t)chunk * N_TOK + koff + k0 + h_c]);
                __half2* pv = reinterpret_cast<__half2*>(&v);
                const __half2* pc = reinterpret_cast<const __half2*>(&cu);
#pragma unroll
                for (int t = 0; t < 4; t++) pv[t] = __hmul2(pv[t], pc[t]);
                aH[l] = v;
            }
        }
        if (!BH) {
#pragma unroll
            for (int l = 0; l < 8; l++) {
                int r = a_r + 16 * l;
                bF[l] = pack_f4(*reinterpret_cast<const float4*>(
                    &Bf[(size_t)(col0 + r) * ldb + koff + k0 + a_c]));
            }
        }
    };

    // reg-path STS into buffer s
    auto stsR = [&](int s) {
        __half* As = Abuf + s * TILE_H;
        __half* Bs = Bbuf + s * TILE_H;
        if (!AH && !SUMS) {
#pragma unroll
            for (int l = 0; l < 8; l++)
                *reinterpret_cast<uint2*>(&As[(a_r + 16 * l) * SSTR + a_c]) = aF[l];
        } else if (MUL_A || SUMS) {
#pragma unroll
            for (int l = 0; l < 4; l++)
                *reinterpret_cast<uint4*>(&As[(h_r + 32 * l) * SSTR + h_c]) = aH[l];
        }
        if (!BH) {
#pragma unroll
            for (int l = 0; l < 8; l++)
                *reinterpret_cast<uint2*>(&Bs[(a_r + 16 * l) * SSTR + a_c]) = bF[l];
        }
    };

    // cp.async staging into buffer s
    auto cpa = [&](int s, int k0) {
        if (A_CP) {
            __half* As = Abuf + s * TILE_H;
#pragma unroll
            for (int l = 0; l < 4; l++) {
                int r = h_r + 32 * l;
                CP_ASYNC16(smem_u32(&As[r * SSTR + h_c]),
                           &Ah[(size_t)(row0 + r) * lda + koff + k0 + h_c]);
            }
        }
        if (B_CP) {
            __half* Bs = Bbuf + s * TILE_H;
#pragma unroll
            for (int l = 0; l < 4; l++) {
                int r = h_r + 32 * l;
                CP_ASYNC16(smem_u32(&Bs[r * SSTR + h_c]),
                           &Bh[(size_t)(col0 + r) * ldb + koff + k0 + h_c]);
            }
        }
    };

    const int grp = lane >> 3;
    const int wi  = lane & 7;

    auto compute = [&](int s) {
        const uint32_t sa  = smem_u32(Abuf + s * TILE_H);
        const uint32_t sbm = smem_u32(Bbuf + s * TILE_H);
#pragma unroll
        for (int ks = 0; ks < 2; ks++) {
            uint32_t af[4][4], bf[8][2];
#pragma unroll
            for (int mt = 0; mt < 4; mt++) {
                int r  = wm * 64 + mt * 16 + (grp & 1) * 8 + wi;
                int kh = ks * 16 + (grp >> 1) * 8;
                LDSM_X4(af[mt][0], af[mt][1], af[mt][2], af[mt][3],
                        sa + (uint32_t)(r * (SSTR * 2) + kh * 2));
            }
#pragma unroll
            for (int hb = 0; hb < 4; hb++) {
                int r  = wn * 64 + hb * 16 + (grp >> 1) * 8 + wi;
                int kh = ks * 16 + (grp & 1) * 8;
                LDSM_X4(bf[2 * hb][0], bf[2 * hb][1],
                        bf[2 * hb + 1][0], bf[2 * hb + 1][1],
                        sbm + (uint32_t)(r * (SSTR * 2) + kh * 2));
            }
#pragma unroll
            for (int mt = 0; mt < 4; mt++)
#pragma unroll
                for (int nt = 0; nt < 8; nt++)
                    MMA_16816(acc[mt][nt], af[mt], bf[nt]);
        }
    };

    // ---- prologue: stage tiles 0, 1 ----
    ldgR(0);  stsR(0); cpa(0, 0);  CP_COMMIT();
    ldgR(32); stsR(1); cpa(1, 32); CP_COMMIT();

    const int niter = K / 32;
    for (int it = 0; it < niter; it++) {
        CP_WAIT1();
        __syncthreads();
        int s  = it % NSTG;
        bool pf = (it + 2 < niter);
        if (pf) ldgR((it + 2) * 32);
        compute(s);
        if (pf) {
            int s2 = (it + 2) % NSTG;
            stsR(s2);
            cpa(s2, (it + 2) * 32);
        }
        CP_COMMIT();
    }

    // ---- epilogue ----
    const int g  = lane >> 2;
    const int tg = lane & 3;
    const int rbase = row0 + wm * 64;
    const int cbase = col0 + wn * 64;

    if (MODE == 1 && STATS) {
        const int chunk = blockIdx.y * 2 + wm;
#pragma unroll
        for (int nt = 0; nt < 8; nt++) {
            float m0 = -INFINITY, m1 = -INFINITY;
#pragma unroll
            for (int mt = 0; mt < 4; mt++)
#pragma unroll
                for (int hh = 0; hh < 2; hh++) {
                    m0 = fmaxf(m0, acc[mt][nt][2 * hh + 0]);
                    m1 = fmaxf(m1, acc[mt][nt][2 * hh + 1]);
                }
            m0 *= scale; m1 *= scale;
#pragma unroll
            for (int msk = 4; msk <= 16; msk <<= 1) {
                m0 = fmaxf(m0, __shfl_xor_sync(0xffffffffu, m0, msk));
                m1 = fmaxf(m1, __shfl_xor_sync(0xffffffffu, m1, msk));
            }
            float s0 = 0.0f, s1 = 0.0f;
#pragma unroll
            for (int mt = 0; mt < 4; mt++)
#pragma unroll
                for (int hh = 0; hh < 2; hh++) {
                    int r = rbase + mt * 16 + g + 8 * hh;
                    int c = cbase + nt * 8 + 2 * tg;
                    float e0 = __expf(acc[mt][nt][2 * hh + 0] * scale - m0);
                    float e1 = __expf(acc[mt][nt][2 * hh + 1] * scale - m1);
                    s0 += e0; s1 += e1;
                    *reinterpret_cast<__half2*>(&Ch[(size_t)r * N + c]) =
                        __floats2half2_rn(e0, e1);
                }
#pragma unroll
            for (int msk = 4; msk <= 16; msk <<= 1) {
                s0 += __shfl_xor_sync(0xffffffffu, s0, msk);
                s1 += __shfl_xor_sync(0xffffffffu, s1, msk);
            }
            if (g == 0) {
                int c = cbase + nt * 8 + 2 * tg;
                pm[(size_t)chunk * N_TOK + c]     = m0;
                pZ[(size_t)chunk * N_TOK + c]     = s0;
                pm[(size_t)chunk * N_TOK + c + 1] = m1;
                pZ[(size_t)chunk * N_TOK + c + 1] = s1;
            }
        }
        return;
    }

#pragma unroll
    for (int mt = 0; mt < 4; mt++)
#pragma unroll
        for (int nt = 0; nt < 8; nt++)
#pragma unroll
            for (int hh = 0; hh < 2; hh++) {
                int r = rbase + mt * 16 + g + 8 * hh;
                int c = cbase + nt * 8 + 2 * tg;
                float o0 = acc[mt][nt][2 * hh + 0];
                float o1 = acc[mt][nt][2 * hh + 1];
                size_t base = (size_t)r * N + c;
                if (MODE == 0) {
                    o0 += bias[c]; o1 += bias[c + 1];
                    if (CH) {
                        *reinterpret_cast<__half2*>(&Ch[base]) =
                            __floats2half2_rn(o0, o1);
                    } else {
                        *reinterpret_cast<float2*>(&Cf[base]) = make_float2(o0, o1);
                    }
                } else {
                    // MODE 3: plain fp16 partial store to slice z
                    __half* dst = Ch + (size_t)blockIdx.z * NH;
                    *reinterpret_cast<__half2*>(&dst[base]) =
                        __floats2half2_rn(o0, o1);
                }
            }
}

// ---------------------------------------------------------------------------
// prep: 5 weight transposes (f32->fp16 NT) + bias concat
// ---------------------------------------------------------------------------
__global__ __launch_bounds__(256) void prep_kernel(
    const float* __restrict__ W1, const float* __restrict__ Wq,
    const float* __restrict__ Wk, const float* __restrict__ Wv,
    const float* __restrict__ W2, const float* __restrict__ bq,
    const float* __restrict__ bk, const float* __restrict__ bv)
{
    const int id  = blockIdx.x;
    const int tid = threadIdx.x;
    if (id >= 384) {
        int i = (id - 384) * 256 + tid;
        g_bqkv[i] = (i < 256) ? bq[i] : (i < 512) ? bk[i - 256] : bv[i - 512];
        return;
    }
    const float* in;
    __half* out;
    int R, Cc, tile;
    if (id < 128)      { in = W1; out = g_W1t;               R = D_IN; Cc = HID;   tile = id; }
    else if (id < 192) { in = Wq; out = g_Wqkvt;             R = HID;  Cc = HID;   tile = id - 128; }
    else if (id < 256) { in = Wk; out = g_Wqkvt + HID * HID; R = HID;  Cc = HID;   tile = id - 192; }
    else if (id < 320) { in = Wv; out = g_Wqkvt + 2 * HID * HID; R = HID; Cc = HID; tile = id - 256; }
    else               { in = W2; out = g_W2t;               R = HID;  Cc = C_OUT; tile = id - 320; }
    int ntx = Cc / 32;
    int c0 = (tile % ntx) * 32, r0 = (tile / ntx) * 32;
    __shared__ float t[32][33];
    int tx = tid & 31, ty = tid >> 5;
#pragma unroll
    for (int i = ty; i < 32; i += 8)
        t[i][tx] = in[(size_t)(r0 + i) * Cc + c0 + tx];
    __syncthreads();
#pragma unroll
    for (int i = ty; i < 32; i += 8)
        out[(size_t)(c0 + i) * R + r0 + tx] = __float2half(t[tx][i]);
}

// vT[n][j] = qkv[j][512+n] * (1-a)
__global__ __launch_bounds__(256) void vT_kernel(const float* __restrict__ aptr)
{
    const int id  = blockIdx.x;
    const int tid = threadIdx.x;
    int n0 = (id & 7) * 32, j0 = (id >> 3) * 32;
    float av = 1.0f - *aptr;
    __shared__ float t[32][33];
    int tx = tid & 31, ty = tid >> 5;
#pragma unroll
    for (int i = ty; i < 32; i += 8)
        t[i][tx] = __half2float(
            g_qkv[(size_t)(j0 + i) * 768 + 512 + n0 + tx]) * av;
    __syncthreads();
#pragma unroll
    for (int i = ty; i < 32; i += 8)
        g_vT[(size_t)(n0 + i) * N_TOK + j0 + tx] = __float2half(t[tx][i]);
}

// combine 128 chunk partials -> c[chunk][j] = exp(pm - LZ) (fp16)
__global__ __launch_bounds__(256) void colstats_combine()
{
    int j = blockIdx.x * 256 + threadIdx.x;
    float mx = -INFINITY, s = 0.0f;
#pragma unroll 8
    for (int c = 0; c < NCHUNK; c++) {
        float mc = g_pm[(size_t)c * N_TOK + j];
        float zc = g_pZ[(size_t)c * N_TOK + j];
        float mn = fmaxf(mx, mc);
        s  = s * __expf(mx - mn) + zc * __expf(mc - mn);
        mx = mn;
    }
    float LZ = mx + logf(s);
#pragma unroll 8
    for (int c = 0; c < NCHUNK; c++)
        g_c[(size_t)c * N_TOK + j] =
            __float2half(__expf(g_pm[(size_t)c * N_TOK + j] - LZ));
}

// ---------------------------------------------------------------------------
extern "C" void kernel_launch(void* const* d_in, const int* in_sizes, int n_in,
                              void* d_out, int out_size)
{
    const float* x  = (const float*)d_in[0];
    const float* W1 = (const float*)d_in[1];
    const float* b1 = (const float*)d_in[2];
    const float* Wq = (const float*)d_in[3];
    const float* bq = (const float*)d_in[4];
    const float* Wk = (const float*)d_in[5];
    const float* bk = (const float*)d_in[6];
    const float* Wv = (const float*)d_in[7];
    const float* bv = (const float*)d_in[8];
    const float* a  = (const float*)d_in[9];
    const float* W2 = (const float*)d_in[10];
    const float* b2 = (const float*)d_in[11];
    float* out = (float*)d_out;

    __half *h, *qkv, *S, *vT, *W1t, *Wqkvt, *W2t, *ctab, *hs;
    float *pm, *pZ, *bqkv;
    cudaGetSymbolAddress((void**)&h,     g_h);
    cudaGetSymbolAddress((void**)&qkv,   g_qkv);
    cudaGetSymbolAddress((void**)&hs,    g_hs);
    cudaGetSymbolAddress((void**)&S,     g_S);
    cudaGetSymbolAddress((void**)&pm,    g_pm);
    cudaGetSymbolAddress((void**)&pZ,    g_pZ);
    cudaGetSymbolAddress((void**)&ctab,  g_c);
    cudaGetSymbolAddress((void**)&W1t,   g_W1t);
    cudaGetSymbolAddress((void**)&Wqkvt, g_Wqkvt);
    cudaGetSymbolAddress((void**)&bqkv,  g_bqkv);
    cudaGetSymbolAddress((void**)&W2t,   g_W2t);
    cudaGetSymbolAddress((void**)&vT,    g_vT);

    const float scale = 0.0625f; // 1/sqrt(256)

    cudaFuncSetAttribute(
        (const void*)hmma_gemm<0, false, false, false, true, true, false>,
        cudaFuncAttributeMaxDynamicSharedMemorySize, SMEM3);
    cudaFuncSetAttribute(
        (const void*)hmma_gemm<0, false, false, true, true, true, false>,
        cudaFuncAttributeMaxDynamicSharedMemorySize, SMEM3);
    cudaFuncSetAttribute(
        (const void*)hmma_gemm<1, false, true, true, true, true, false>,
        cudaFuncAttributeMaxDynamicSharedMemorySize, SMEM3);
    cudaFuncSetAttribute(
        (const void*)hmma_gemm<3, true, false, true, true, true, false>,
        cudaFuncAttributeMaxDynamicSharedMemorySize, SMEM3);
    cudaFuncSetAttribute(
        (const void*)hmma_gemm<0, false, false, true, true, false, true>,
        cudaFuncAttributeMaxDynamicSharedMemorySize, SMEM3);

    // 0) weights + bias prep
    prep_kernel<<<387, 256>>>(W1, Wq, Wk, Wv, W2, bq, bk, bv);
    // 1) h = x @ W1 + b1
    hmma_gemm<0, false, false, false, true, true, false>
        <<<dim3(HID / 128, N_TOK / 128, 1), 128, SMEM3>>>(
        x, W1t, h, HID, D_IN, D_IN, D_IN, b1, 0.f, nullptr, nullptr, nullptr,
        nullptr, nullptr);
    // 2) qkv = h @ Wqkv + bqkv
    hmma_gemm<0, false, false, true, true, true, false>
        <<<dim3(768 / 128, N_TOK / 128, 1), 128, SMEM3>>>(
        h, Wqkvt, qkv, 768, HID, HID, HID, bqkv, 0.f, nullptr, nullptr, nullptr,
        nullptr, nullptr);
    // 3) vT = (v*(1-a))^T
    vT_kernel<<<2048, 256>>>(a);
    // 4) S-GEMM: store Etilde = exp(qk*scale - m_chunk), per-chunk stats
    hmma_gemm<1, false, true, true, true, true, false>
        <<<dim3(N_TOK / 128, N_TOK / 128, 1), 128, SMEM3>>>(
        qkv, qkv + HID, S, N_TOK, HID, 768, 768, nullptr, scale, nullptr, pm, pZ,
        nullptr, nullptr);
    // 5) combine -> c table
    colstats_combine<<<N_TOK / 256, 256>>>();
    // 6) hs[z] = (Etilde * c)_z @ vT^T  (split-K=4, plain fp16 slice stores)
    hmma_gemm<3, true, false, true, true, true, false>
        <<<dim3(HID / 128, N_TOK / 128, NSPLIT), 128, SMEM3>>>(
        S, vT, hs, HID, N_TOK / NSPLIT, N_TOK, N_TOK, nullptr, 0.f, ctab,
        nullptr, nullptr, nullptr, nullptr);
    // 7) out = (a*h + sum hs) @ W2 + b2   (gated residual folded into staging)
    hmma_gemm<0, false, false, true, true, false, true>
        <<<dim3(C_OUT / 128, N_TOK / 128, 1), 128, SMEM3>>>(
        h, W2t, out, C_OUT, HID, HID, HID, b2, 0.f, nullptr, nullptr, nullptr,
        hs, a);

    (void)in_sizes; (void)n_in; (void)out_size;
}

// round 17
// speedup vs baseline: 1.0370x; 1.0370x over previous
#include <cuda_runtime.h>
#include <cuda_fp16.h>
#include <stdint.h>
#include <math.h>

#define N_TOK 8192
#define D_IN  512
#define HID   256
#define C_OUT 256
#define NCHUNK 128           // one stats chunk per 64-row warp block

// ---- scratch (static __device__, allocation-free) ----
__device__ __half g_h  [N_TOK * HID];
__device__ __half g_qk [N_TOK * 2 * HID];          // [8192][512] q|k
__device__ float  g_h2 [N_TOK * HID];              // f32 (atomic accum)
__device__ __half g_S  [(size_t)N_TOK * N_TOK];    // Etilde = exp(S*scale - m_chunk)
__device__ float  g_pm [NCHUNK * N_TOK];
__device__ float  g_pZ [NCHUNK * N_TOK];
__device__ __half g_c  [NCHUNK * N_TOK];           // exp(pm - LZ)
__device__ __half g_W1t[HID * D_IN];
__device__ __half g_Wqkt[2 * HID * HID];           // Wq^T | Wk^T
__device__ float  g_bqk[2 * HID];
__device__ __half g_WvT[HID * HID];                // Wv^T
__device__ __half g_W2t[C_OUT * HID];
__device__ __half g_vT [HID * N_TOK];              // (v*(1-a))^T : [256][8192]

__device__ __forceinline__ uint32_t smem_u32(const void* p) {
    uint32_t a;
    asm("{ .reg .u64 t; cvta.to.shared.u64 t, %1; cvt.u32.u64 %0, t; }"
        : "=r"(a) : "l"(p));
    return a;
}

__device__ __forceinline__ uint2 pack_f4(float4 v) {
    __half2 h0 = __floats2half2_rn(v.x, v.y);
    __half2 h1 = __floats2half2_rn(v.z, v.w);
    uint2 u;
    u.x = *reinterpret_cast<uint32_t*>(&h0);
    u.y = *reinterpret_cast<uint32_t*>(&h1);
    return u;
}

#define LDSM_X4(r0, r1, r2, r3, addr) \
    asm volatile("ldmatrix.sync.aligned.m8n8.x4.shared.b16 {%0,%1,%2,%3}, [%4];" \
        : "=r"(r0), "=r"(r1), "=r"(r2), "=r"(r3) : "r"(addr))

#define MMA_16816(c, a, b) \
    asm volatile("mma.sync.aligned.m16n8k16.row.col.f32.f16.f16.f32 " \
        "{%0,%1,%2,%3}, {%4,%5,%6,%7}, {%8,%9}, {%0,%1,%2,%3};" \
        : "+f"((c)[0]), "+f"((c)[1]), "+f"((c)[2]), "+f"((c)[3]) \
        : "r"((a)[0]), "r"((a)[1]), "r"((a)[2]), "r"((a)[3]), \
          "r"((b)[0]), "r"((b)[1]))

#define CP_ASYNC16(dst, src) \
    asm volatile("cp.async.cg.shared.global [%0], [%1], 16;" \
        :: "r"(dst), "l"(src) : "memory")
#define CP_COMMIT() asm volatile("cp.async.commit_group;" ::: "memory")
#define CP_WAIT1()  asm volatile("cp.async.wait_group 1;" ::: "memory")

#define SSTR 40    // smem row stride in halves; conflict-free LDSM phases
#define NSTG 3     // pipeline stages
#define TILE_H (128 * SSTR)                 // halves per tile buffer
#define SMEM3 (NSTG * 2 * TILE_H * 2)       // bytes of dynamic smem (61440)

// ---------------------------------------------------------------------------
// fp16 NT GEMM: C[M,N] = A[M,K'] @ Bt[N,K']^T, K' slice per grid.z.
// MODE 0: C = acc + bias[col]   (AUX: also store aux = (*aptr) * C, f32)
// MODE 1 + STATS: per-warp(64-row) column softmax store + chunk stats pm/pZ.
// MODE 3: atomicAdd(C, acc)     (split-K, C f32)
// MODE 4: C = (1 - *aptr) * (acc + bias[row]), C fp16   (vT-GEMM)
// AH/BH: A/B gmem fp16 (else f32). CH: C stored fp16.
// MUL_A: A (fp16) multiplied by ctab[rowchunk][kcol] during staging.
// fp16 operands without MUL stage via cp.async (3-stage ring); f32 / MUL_A
// operands stage via register prefetch one iter ahead.
// CTA 128x128, BK=32, 128 threads (4 warps 2x2), warp tile 64x64.
// ---------------------------------------------------------------------------
template <int MODE, bool MUL_A, bool STATS, bool AH, bool BH, bool CH, bool AUX>
__global__ __launch_bounds__(128, 2) void hmma_gemm(
    const void* __restrict__ Av, const void* __restrict__ Bv,
    void* __restrict__ Cv, int N, int K, int lda, int ldb,
    const float* __restrict__ bias, float scale,
    const __half* __restrict__ ctab,
    float* __restrict__ pm, float* __restrict__ pZ,
    float* __restrict__ aux, const float* __restrict__ aptr)
{
    constexpr bool A_CP = (AH && !MUL_A);   // A staged via cp.async
    constexpr bool B_CP = BH;               // B staged via cp.async

    const float*  Af = (const float*)Av;
    const __half* Ah = (const __half*)Av;
    const float*  Bf = (const float*)Bv;
    const __half* Bh = (const __half*)Bv;
    float*  Cf = (float*)Cv;
    __half* Ch = (__half*)Cv;

    extern __shared__ __half dynsm[];
    __half* const Abuf = dynsm;                    // [NSTG][TILE_H]
    __half* const Bbuf = dynsm + NSTG * TILE_H;    // [NSTG][TILE_H]

    const int tid  = threadIdx.x;
    const int lane = tid & 31;
    const int wid  = tid >> 5;          // 0..3
    const int wm   = wid >> 1;          // 0..1
    const int wn   = wid & 1;           // 0..1
    const int row0 = blockIdx.y * 128;
    const int col0 = blockIdx.x * 128;
    const int koff = blockIdx.z * K;

    const int h_r = tid >> 2;           // 0..31 (f16 staging, 4 passes)
    const int h_c = (tid & 3) * 8;
    const int a_r = tid >> 3;           // 0..15 (f32 staging, 8 passes)
    const int a_c = (tid & 7) * 4;

    float acc[4][8][4];
#pragma unroll
    for (int i = 0; i < 4; i++)
#pragma unroll
        for (int j = 0; j < 8; j++)
#pragma unroll
            for (int r = 0; r < 4; r++) acc[i][j][r] = 0.0f;

    uint2 aF[8], bF[8];
    uint4 aH[4];

    // reg-path LDG (issued early; consumed by stsR)
    auto ldgR = [&](int k0) {
        if (!AH) {
#pragma unroll
            for (int l = 0; l < 8; l++) {
                int r = a_r + 16 * l;
                aF[l] = pack_f4(*reinterpret_cast<const float4*>(
                    &Af[(size_t)(row0 + r) * lda + koff + k0 + a_c]));
            }
        } else if (MUL_A) {
#pragma unroll
            for (int l = 0; l < 4; l++) {
                int r = h_r + 32 * l;
                uint4 v = *reinterpret_cast<const uint4*>(
                    &Ah[(size_t)(row0 + r) * lda + koff + k0 + h_c]);
                int chunk = (row0 + r) >> 6;
                uint4 cu = *reinterpret_cast<const uint4*>(
                    &ctab[(size_t)chunk * N_TOK + koff + k0 + h_c]);
                __half2* pv = reinterpret_cast<__half2*>(&v);
                const __half2* pc = reinterpret_cast<const __half2*>(&cu);
#pragma unroll
                for (int t = 0; t < 4; t++) pv[t] = __hmul2(pv[t], pc[t]);
                aH[l] = v;
            }
        }
        if (!BH) {
#pragma unroll
            for (int l = 0; l < 8; l++) {
                int r = a_r + 16 * l;
                bF[l] = pack_f4(*reinterpret_cast<const float4*>(
                    &Bf[(size_t)(col0 + r) * ldb + koff + k0 + a_c]));
            }
        }
    };

    // reg-path STS into buffer s
    auto stsR = [&](int s) {
        __half* As = Abuf + s * TILE_H;
        __half* Bs = Bbuf + s * TILE_H;
        if (!AH) {
#pragma unroll
            for (int l = 0; l < 8; l++)
                *reinterpret_cast<uint2*>(&As[(a_r + 16 * l) * SSTR + a_c]) = aF[l];
        } else if (MUL_A) {
#pragma unroll
            for (int l = 0; l < 4; l++)
                *reinterpret_cast<uint4*>(&As[(h_r + 32 * l) * SSTR + h_c]) = aH[l];
        }
        if (!BH) {
#pragma unroll
            for (int l = 0; l < 8; l++)
                *reinterpret_cast<uint2*>(&Bs[(a_r + 16 * l) * SSTR + a_c]) = bF[l];
        }
    };

    // cp.async staging into buffer s
    auto cpa = [&](int s, int k0) {
        if (A_CP) {
            __half* As = Abuf + s * TILE_H;
#pragma unroll
            for (int l = 0; l < 4; l++) {
                int r = h_r + 32 * l;
                CP_ASYNC16(smem_u32(&As[r * SSTR + h_c]),
                           &Ah[(size_t)(row0 + r) * lda + koff + k0 + h_c]);
            }
        }
        if (B_CP) {
            __half* Bs = Bbuf + s * TILE_H;
#pragma unroll
            for (int l = 0; l < 4; l++) {
                int r = h_r + 32 * l;
                CP_ASYNC16(smem_u32(&Bs[r * SSTR + h_c]),
                           &Bh[(size_t)(col0 + r) * ldb + koff + k0 + h_c]);
            }
        }
    };

    const int grp = lane >> 3;
    const int wi  = lane & 7;

    auto compute = [&](int s) {
        const uint32_t sa  = smem_u32(Abuf + s * TILE_H);
        const uint32_t sbm = smem_u32(Bbuf + s * TILE_H);
#pragma unroll
        for (int ks = 0; ks < 2; ks++) {
            uint32_t af[4][4], bf[8][2];
#pragma unroll
            for (int mt = 0; mt < 4; mt++) {
                int r  = wm * 64 + mt * 16 + (grp & 1) * 8 + wi;
                int kh = ks * 16 + (grp >> 1) * 8;
                LDSM_X4(af[mt][0], af[mt][1], af[mt][2], af[mt][3],
                        sa + (uint32_t)(r * (SSTR * 2) + kh * 2));
            }
#pragma unroll
            for (int hb = 0; hb < 4; hb++) {
                int r  = wn * 64 + hb * 16 + (grp >> 1) * 8 + wi;
                int kh = ks * 16 + (grp & 1) * 8;
                LDSM_X4(bf[2 * hb][0], bf[2 * hb][1],
                        bf[2 * hb + 1][0], bf[2 * hb + 1][1],
                        sbm + (uint32_t)(r * (SSTR * 2) + kh * 2));
            }
#pragma unroll
            for (int mt = 0; mt < 4; mt++)
#pragma unroll
                for (int nt = 0; nt < 8; nt++)
                    MMA_16816(acc[mt][nt], af[mt], bf[nt]);
        }
    };

    // ---- prologue: stage tiles 0, 1 ----
    ldgR(0);  stsR(0); cpa(0, 0);  CP_COMMIT();
    ldgR(32); stsR(1); cpa(1, 32); CP_COMMIT();

    const int niter = K / 32;
    for (int it = 0; it < niter; it++) {
        CP_WAIT1();
        __syncthreads();
        int s  = it % NSTG;
        bool pf = (it + 2 < niter);
        if (pf) ldgR((it + 2) * 32);
        compute(s);
        if (pf) {
            int s2 = (it + 2) % NSTG;
            stsR(s2);
            cpa(s2, (it + 2) * 32);
        }
        CP_COMMIT();
    }

    // ---- epilogue ----
    const int g  = lane >> 2;
    const int tg = lane & 3;
    const int rbase = row0 + wm * 64;
    const int cbase = col0 + wn * 64;

    if (MODE == 1 && STATS) {
        const int chunk = blockIdx.y * 2 + wm;
#pragma unroll
        for (int nt = 0; nt < 8; nt++) {
            float m0 = -INFINITY, m1 = -INFINITY;
#pragma unroll
            for (int mt = 0; mt < 4; mt++)
#pragma unroll
                for (int hh = 0; hh < 2; hh++) {
                    m0 = fmaxf(m0, acc[mt][nt][2 * hh + 0]);
                    m1 = fmaxf(m1, acc[mt][nt][2 * hh + 1]);
                }
            m0 *= scale; m1 *= scale;
#pragma unroll
            for (int msk = 4; msk <= 16; msk <<= 1) {
                m0 = fmaxf(m0, __shfl_xor_sync(0xffffffffu, m0, msk));
                m1 = fmaxf(m1, __shfl_xor_sync(0xffffffffu, m1, msk));
            }
            float s0 = 0.0f, s1 = 0.0f;
#pragma unroll
            for (int mt = 0; mt < 4; mt++)
#pragma unroll
                for (int hh = 0; hh < 2; hh++) {
                    int r = rbase + mt * 16 + g + 8 * hh;
                    int c = cbase + nt * 8 + 2 * tg;
                    float e0 = __expf(acc[mt][nt][2 * hh + 0] * scale - m0);
                    float e1 = __expf(acc[mt][nt][2 * hh + 1] * scale - m1);
                    s0 += e0; s1 += e1;
                    *reinterpret_cast<__half2*>(&Ch[(size_t)r * N + c]) =
                        __floats2half2_rn(e0, e1);
                }
#pragma unroll
            for (int msk = 4; msk <= 16; msk <<= 1) {
                s0 += __shfl_xor_sync(0xffffffffu, s0, msk);
                s1 += __shfl_xor_sync(0xffffffffu, s1, msk);
            }
            if (g == 0) {
                int c = cbase + nt * 8 + 2 * tg;
                pm[(size_t)chunk * N_TOK + c]     = m0;
                pZ[(size_t)chunk * N_TOK + c]     = s0;
                pm[(size_t)chunk * N_TOK + c + 1] = m1;
                pZ[(size_t)chunk * N_TOK + c + 1] = s1;
            }
        }
        return;
    }

    float av = 0.0f;
    if (AUX)          av = *aptr;
    if (MODE == 4)    av = 1.0f - *aptr;
#pragma unroll
    for (int mt = 0; mt < 4; mt++)
#pragma unroll
        for (int nt = 0; nt < 8; nt++)
#pragma unroll
            for (int hh = 0; hh < 2; hh++) {
                int r = rbase + mt * 16 + g + 8 * hh;
                int c = cbase + nt * 8 + 2 * tg;
                float o0 = acc[mt][nt][2 * hh + 0];
                float o1 = acc[mt][nt][2 * hh + 1];
                size_t base = (size_t)r * N + c;
                if (MODE == 0) {
                    o0 += bias[c]; o1 += bias[c + 1];
                    if (CH) {
                        *reinterpret_cast<__half2*>(&Ch[base]) =
                            __floats2half2_rn(o0, o1);
                    } else {
                        *reinterpret_cast<float2*>(&Cf[base]) = make_float2(o0, o1);
                    }
                    if (AUX)
                        *reinterpret_cast<float2*>(&aux[base]) =
                            make_float2(av * o0, av * o1);
                } else if (MODE == 4) {
                    float bv_ = bias[r];
                    o0 = av * (o0 + bv_);
                    o1 = av * (o1 + bv_);
                    *reinterpret_cast<__half2*>(&Ch[base]) =
                        __floats2half2_rn(o0, o1);
                } else {
                    atomicAdd(&Cf[base],     o0);
                    atomicAdd(&Cf[base + 1], o1);
                }
            }
}

// ---------------------------------------------------------------------------
// prep: 5 weight transposes (f32->fp16 NT) + q|k bias concat
// ---------------------------------------------------------------------------
__global__ __launch_bounds__(256) void prep_kernel(
    const float* __restrict__ W1, const float* __restrict__ Wq,
    const float* __restrict__ Wk, const float* __restrict__ Wv,
    const float* __restrict__ W2, const float* __restrict__ bq,
    const float* __restrict__ bk)
{
    const int id  = blockIdx.x;
    const int tid = threadIdx.x;
    if (id >= 384) {
        int i = (id - 384) * 256 + tid;   // 0..511
        g_bqk[i] = (i < 256) ? bq[i] : bk[i - 256];
        return;
    }
    const float* in;
    __half* out;
    int R, Cc, tile;
    if (id < 128)      { in = W1; out = g_W1t;              R = D_IN; Cc = HID;   tile = id; }
    else if (id < 192) { in = Wq; out = g_Wqkt;             R = HID;  Cc = HID;   tile = id - 128; }
    else if (id < 256) { in = Wk; out = g_Wqkt + HID * HID; R = HID;  Cc = HID;   tile = id - 192; }
    else if (id < 320) { in = Wv; out = g_WvT;              R = HID;  Cc = HID;   tile = id - 256; }
    else               { in = W2; out = g_W2t;              R = HID;  Cc = C_OUT; tile = id - 320; }
    int ntx = Cc / 32;
    int c0 = (tile % ntx) * 32, r0 = (tile / ntx) * 32;
    __shared__ float t[32][33];
    int tx = tid & 31, ty = tid >> 5;
#pragma unroll
    for (int i = ty; i < 32; i += 8)
        t[i][tx] = in[(size_t)(r0 + i) * Cc + c0 + tx];
    __syncthreads();
#pragma unroll
    for (int i = ty; i < 32; i += 8)
        out[(size_t)(c0 + i) * R + r0 + tx] = __float2half(t[tx][i]);
}

// h2 = a * h  (fp16 h produced by h-GEMM AUX path writes this; kept for clarity)

// combine 128 chunk partials -> c[chunk][j] = exp(pm - LZ) (fp16)
// warp-per-column: grid 2048 x 128 threads (4 warps/block)
__global__ __launch_bounds__(128) void colstats_combine()
{
    int j    = blockIdx.x * 4 + (threadIdx.x >> 5);
    int lane = threadIdx.x & 31;
    float pmv[4];
    float m = -INFINITY, s = 0.0f;
#pragma unroll
    for (int t = 0; t < 4; t++) {
        int c = lane + 32 * t;
        float mc = g_pm[(size_t)c * N_TOK + j];
        float zc = g_pZ[(size_t)c * N_TOK + j];
        pmv[t] = mc;
        float mn = fmaxf(m, mc);
        s = s * __expf(m - mn) + zc * __expf(mc - mn);
        m = mn;
    }
#pragma unroll
    for (int msk = 1; msk <= 16; msk <<= 1) {
        float om = __shfl_xor_sync(0xffffffffu, m, msk);
        float os = __shfl_xor_sync(0xffffffffu, s, msk);
        float mn = fmaxf(m, om);
        s = s * __expf(m - mn) + os * __expf(om - mn);
        m = mn;
    }
    float LZ = m + logf(s);
#pragma unroll
    for (int t = 0; t < 4; t++) {
        int c = lane + 32 * t;
        g_c[(size_t)c * N_TOK + j] = __float2half(__expf(pmv[t] - LZ));
    }
}

// ---------------------------------------------------------------------------
extern "C" void kernel_launch(void* const* d_in, const int* in_sizes, int n_in,
                              void* d_out, int out_size)
{
    const float* x  = (const float*)d_in[0];
    const float* W1 = (const float*)d_in[1];
    const float* b1 = (const float*)d_in[2];
    const float* Wq = (const float*)d_in[3];
    const float* bq = (const float*)d_in[4];
    const float* Wk = (const float*)d_in[5];
    const float* bk = (const float*)d_in[6];
    const float* Wv = (const float*)d_in[7];
    const float* bv = (const float*)d_in[8];
    const float* a  = (const float*)d_in[9];
    const float* W2 = (const float*)d_in[10];
    const float* b2 = (const float*)d_in[11];
    float* out = (float*)d_out;

    __half *h, *qk, *S, *vT, *W1t, *Wqkt, *WvT, *W2t, *ctab;
    float *h2, *pm, *pZ, *bqk;
    cudaGetSymbolAddress((void**)&h,    g_h);
    cudaGetSymbolAddress((void**)&qk,   g_qk);
    cudaGetSymbolAddress((void**)&h2,   g_h2);
    cudaGetSymbolAddress((void**)&S,    g_S);
    cudaGetSymbolAddress((void**)&pm,   g_pm);
    cudaGetSymbolAddress((void**)&pZ,   g_pZ);
    cudaGetSymbolAddress((void**)&ctab, g_c);
    cudaGetSymbolAddress((void**)&W1t,  g_W1t);
    cudaGetSymbolAddress((void**)&Wqkt, g_Wqkt);
    cudaGetSymbolAddress((void**)&bqk,  g_bqk);
    cudaGetSymbolAddress((void**)&WvT,  g_WvT);
    cudaGetSymbolAddress((void**)&W2t,  g_W2t);
    cudaGetSymbolAddress((void**)&vT,   g_vT);

    const float scale = 0.0625f; // 1/sqrt(256)

    cudaFuncSetAttribute(
        (const void*)hmma_gemm<0, false, false, false, true, true, true>,
        cudaFuncAttributeMaxDynamicSharedMemorySize, SMEM3);
    cudaFuncSetAttribute(
        (const void*)hmma_gemm<0, false, false, true, true, true, false>,
        cudaFuncAttributeMaxDynamicSharedMemorySize, SMEM3);
    cudaFuncSetAttribute(
        (const void*)hmma_gemm<4, false, false, true, true, true, false>,
        cudaFuncAttributeMaxDynamicSharedMemorySize, SMEM3);
    cudaFuncSetAttribute(
        (const void*)hmma_gemm<1, false, true, true, true, true, false>,
        cudaFuncAttributeMaxDynamicSharedMemorySize, SMEM3);
    cudaFuncSetAttribute(
        (const void*)hmma_gemm<3, true, false, true, true, false, false>,
        cudaFuncAttributeMaxDynamicSharedMemorySize, SMEM3);
    cudaFuncSetAttribute(
        (const void*)hmma_gemm<0, false, false, false, true, false, false>,
        cudaFuncAttributeMaxDynamicSharedMemorySize, SMEM3);

    // 0) weights + bias prep
    prep_kernel<<<386, 256>>>(W1, Wq, Wk, Wv, W2, bq, bk);
    // 1) h = x @ W1 + b1  (also h2 = a*h via AUX)
    hmma_gemm<0, false, false, false, true, true, true>
        <<<dim3(HID / 128, N_TOK / 128, 1), 128, SMEM3>>>(
        x, W1t, h, HID, D_IN, D_IN, D_IN, b1, 0.f, nullptr, nullptr, nullptr, h2, a);
    // 2) qk = h @ Wqk + bqk  (N=512)
    hmma_gemm<0, false, false, true, true, true, false>
        <<<dim3(512 / 128, N_TOK / 128, 1), 128, SMEM3>>>(
        h, Wqkt, qk, 512, HID, HID, HID, bqk, 0.f, nullptr, nullptr, nullptr,
        nullptr, nullptr);
    // 3) vT = (1-a) * (Wv^T @ h^T + bv[row])   (MODE 4 GEMM)
    hmma_gemm<4, false, false, true, true, true, false>
        <<<dim3(N_TOK / 128, HID / 128, 1), 128, SMEM3>>>(
        WvT, h, vT, N_TOK, HID, HID, HID, bv, 0.f, nullptr, nullptr, nullptr,
        nullptr, a);
    // 4) S-GEMM: store Etilde = exp(qk*scale - m_chunk), per-chunk stats
    hmma_gemm<1, false, true, true, true, true, false>
        <<<dim3(N_TOK / 128, N_TOK / 128, 1), 128, SMEM3>>>(
        qk, qk + HID, S, N_TOK, HID, 512, 512, nullptr, scale, nullptr, pm, pZ,
        nullptr, nullptr);
    // 5) combine -> c table (warp per column)
    colstats_combine<<<N_TOK / 4, 128>>>();
    // 6) h2 += (Etilde * c) @ vT^T   (split-K=2, atomic f32)
    hmma_gemm<3, true, false, true, true, false, false>
        <<<dim3(HID / 128, N_TOK / 128, 2), 128, SMEM3>>>(
        S, vT, h2, HID, N_TOK / 2, N_TOK, N_TOK, nullptr, 0.f, ctab, nullptr, nullptr,
        nullptr, nullptr);
    // 7) out = h2 @ W2 + b2
    hmma_gemm<0, false, false, false, true, false, false>
        <<<dim3(C_OUT / 128, N_TOK / 128, 1), 128, SMEM3>>>(
        h2, W2t, out, C_OUT, HID, HID, HID, b2, 0.f, nullptr, nullptr, nullptr,
        nullptr, nullptr);

    (void)in_sizes; (void)n_in; (void)out_size;
}